// round 4
// baseline (speedup 1.0000x reference)
#include <cuda_runtime.h>

#define MAXN 100000
#define MAXE 600000
#define F1 128
#define F2 64

// Scratch: __device__ globals (allocation-free rule), referenced directly as symbols.
__device__ float g_h1[MAXN * F1];    // x @ W1
__device__ float g_agg1[MAXN * F1];  // aggregated layer-1 (pre-bias/relu)
__device__ float g_h2[MAXN * F2];    // relu(agg1+b1) @ W2
__device__ float g_dinv[MAXN];       // deg -> rsqrt(deg)
__device__ int   g_eidx[2 * MAXE];   // normalized int32 edge index [src | dst]
__device__ int   g_is32;             // 1 if raw edge buffer is int32, 0 if int64

// ---------------- edge dtype detection + normalization ----------------
// Single block. Scan the buffer as int64 over [0, E) (safe under both layouts:
// int64 => 2E elements exist; int32 => E int64-sized slots exist).
// True int64 data: all values in [0, n). int32 misread as int64: huge values.
__global__ void detect_kernel(const void* __restrict__ ei_raw, int E, int n) {
    __shared__ int bad;
    if (threadIdx.x == 0) bad = 0;
    __syncthreads();
    const long long* p = (const long long*)ei_raw;
    int lbad = 0;
    for (int i = threadIdx.x; i < E; i += blockDim.x) {
        long long v = p[i];
        if (v < 0 || v >= (long long)n) lbad = 1;
    }
    if (lbad) atomicOr(&bad, 1);
    __syncthreads();
    if (threadIdx.x == 0) g_is32 = bad;  // bad int64 interpretation => it's int32
}

__global__ void convert_kernel(const void* __restrict__ ei_raw, int E, int n) {
    int i = blockIdx.x * blockDim.x + threadIdx.x;
    if (i >= 2 * E) return;
    int v;
    if (g_is32) v = ((const int*)ei_raw)[i];
    else        v = (int)((const long long*)ei_raw)[i];
    // defensive clamp: a bad index becomes wrong-answer signal, not a device trap
    v = v < 0 ? 0 : (v >= n ? n - 1 : v);
    g_eidx[i] = v;
}

// ---------------- degree / norm ----------------
__global__ void deg_init_kernel(int n) {
    int i = blockIdx.x * blockDim.x + threadIdx.x;
    if (i < n) g_dinv[i] = 1.0f;  // self-loop
}

__global__ void deg_count_kernel(int E) {
    int e = blockIdx.x * blockDim.x + threadIdx.x;
    if (e < E) atomicAdd(&g_dinv[g_eidx[E + e]], 1.0f);
}

__global__ void deg_rsqrt_kernel(int n) {
    int i = blockIdx.x * blockDim.x + threadIdx.x;
    if (i < n) g_dinv[i] = rsqrtf(g_dinv[i]);
}

// ---------------- GEMM ----------------
// LAYER2=false: C=g_h1, A=x (param),             no activation
// LAYER2=true : C=g_h2, A=g_agg1 (symbol), A-load fused with +b1,relu
template <int BN, int TN, bool LAYER2>
__global__ __launch_bounds__(256)
void gemm_kernel(const float* __restrict__ Ain, const float* __restrict__ W,
                 const float* __restrict__ bias, int M) {
    constexpr int BM = 64, BK = 32, K = 128;
    constexpr int TM = 4;
    constexpr int NTX = BN / TN;  // 16
    constexpr int NTY = BM / TM;  // 16
    static_assert(NTX * NTY == 256, "thread layout");

    __shared__ alignas(16) float As[BM][BK + 4];  // row stride 144B (16B multiple)
    __shared__ alignas(16) float Bs[BK][BN];
    __shared__ alignas(16) float bsh[K];

    const float* A = LAYER2 ? (const float*)g_agg1 : Ain;
    float* C = LAYER2 ? g_h2 : g_h1;

    const int tid = threadIdx.x;
    const int tx = tid % NTX;
    const int ty = tid / NTX;
    const int row0 = blockIdx.x * BM;

    if constexpr (LAYER2) {
        if (tid < K) bsh[tid] = bias[tid];
    }

    float acc[TM][TN];
#pragma unroll
    for (int m = 0; m < TM; m++)
#pragma unroll
        for (int j = 0; j < TN; j++) acc[m][j] = 0.0f;

    for (int k0 = 0; k0 < K; k0 += BK) {
        __syncthreads();
        // A tile: BM x BK = 2048 floats = 512 float4 (2 per thread)
#pragma unroll
        for (int i = 0; i < (BM * BK) / (256 * 4); i++) {
            int t = tid + i * 256;
            int r = t >> 3;   // / (BK/4)
            int c4 = t & 7;   // % (BK/4)
            float4 v = make_float4(0.f, 0.f, 0.f, 0.f);
            int grow = row0 + r;
            if (grow < M)
                v = *reinterpret_cast<const float4*>(&A[(size_t)grow * K + k0 + c4 * 4]);
            if constexpr (LAYER2) {
                int kk = k0 + c4 * 4;
                v.x = fmaxf(v.x + bsh[kk + 0], 0.f);
                v.y = fmaxf(v.y + bsh[kk + 1], 0.f);
                v.z = fmaxf(v.z + bsh[kk + 2], 0.f);
                v.w = fmaxf(v.w + bsh[kk + 3], 0.f);
            }
            *reinterpret_cast<float4*>(&As[r][c4 * 4]) = v;
        }
        // W tile: BK x BN
#pragma unroll
        for (int i = 0; i < (BK * BN) / (256 * 4); i++) {
            int t = tid + i * 256;
            int r = t / (BN / 4);
            int c4 = t % (BN / 4);
            *reinterpret_cast<float4*>(&Bs[r][c4 * 4]) =
                *reinterpret_cast<const float4*>(&W[(size_t)(k0 + r) * BN + c4 * 4]);
        }
        __syncthreads();

#pragma unroll
        for (int k = 0; k < BK; k++) {
            float a[TM];
#pragma unroll
            for (int m = 0; m < TM; m++) a[m] = As[ty * TM + m][k];
            float b[TN];
#pragma unroll
            for (int j = 0; j < TN; j += 4) {
                float4 bv = *reinterpret_cast<const float4*>(&Bs[k][tx * TN + j]);
                b[j] = bv.x; b[j + 1] = bv.y; b[j + 2] = bv.z; b[j + 3] = bv.w;
            }
#pragma unroll
            for (int m = 0; m < TM; m++)
#pragma unroll
                for (int j = 0; j < TN; j++)
                    acc[m][j] = fmaf(a[m], b[j], acc[m][j]);
        }
    }

#pragma unroll
    for (int m = 0; m < TM; m++) {
        int grow = row0 + ty * TM + m;
        if (grow < M) {
#pragma unroll
            for (int j = 0; j < TN; j += 4) {
                float4 v = make_float4(acc[m][j], acc[m][j + 1], acc[m][j + 2], acc[m][j + 3]);
                *reinterpret_cast<float4*>(&C[(size_t)grow * BN + tx * TN + j]) = v;
            }
        }
    }
}

// ---------------- aggregation ----------------
// layer1 self-loop init: g_agg1 = dinv^2 * g_h1
__global__ void init1_kernel(int n) {
    int idx = blockIdx.x * blockDim.x + threadIdx.x;
    int total = n * (F1 / 4);
    if (idx < total) {
        int i = idx / (F1 / 4);
        float di = g_dinv[i];
        float w = di * di;
        float4 v = reinterpret_cast<const float4*>(g_h1)[idx];
        v.x *= w; v.y *= w; v.z *= w; v.w *= w;
        reinterpret_cast<float4*>(g_agg1)[idx] = v;
    }
}

// layer2 self-loop init + bias: out = dinv^2 * g_h2 + b2 (writes d_out directly)
__global__ void init2_kernel(const float* __restrict__ b2, float* __restrict__ out, int n) {
    int idx = blockIdx.x * blockDim.x + threadIdx.x;
    int total = n * (F2 / 4);
    if (idx < total) {
        int i = idx / (F2 / 4);
        int c4 = idx % (F2 / 4);
        float di = g_dinv[i];
        float w = di * di;
        float4 v = reinterpret_cast<const float4*>(g_h2)[idx];
        float4 b = reinterpret_cast<const float4*>(b2)[c4];
        v.x = fmaf(v.x, w, b.x);
        v.y = fmaf(v.y, w, b.y);
        v.z = fmaf(v.z, w, b.z);
        v.w = fmaf(v.w, w, b.w);
        reinterpret_cast<float4*>(out)[idx] = v;
    }
}

// One warp per edge: gather src row, scale by dinv[s]*dinv[d], atomic-add into dst row.
// F==F1: h=g_h1, acc=g_agg1 (symbols). F==F2: h=g_h2, acc=outp (d_out).
template <int F>
__global__ void scatter_kernel(float* __restrict__ outp, int E) {
    int gw = (blockIdx.x * blockDim.x + threadIdx.x) >> 5;
    if (gw >= E) return;
    int lane = threadIdx.x & 31;
    int s = g_eidx[gw];
    int d = g_eidx[E + gw];
    float w = g_dinv[s] * g_dinv[d];
    const float* h = (F == F1) ? (const float*)g_h1 : (const float*)g_h2;
    float* acc = (F == F1) ? (float*)g_agg1 : outp;
    constexpr int PER = F / 32;  // 4 or 2
    const float* hs = h + (size_t)s * F + lane * PER;
    float* ad = acc + (size_t)d * F + lane * PER;
    if (PER == 4) {
        float4 v = *reinterpret_cast<const float4*>(hs);
        atomicAdd(ad + 0, v.x * w);
        atomicAdd(ad + 1, v.y * w);
        atomicAdd(ad + 2, v.z * w);
        atomicAdd(ad + 3, v.w * w);
    } else {
        float2 v = *reinterpret_cast<const float2*>(hs);
        atomicAdd(ad + 0, v.x * w);
        atomicAdd(ad + 1, v.y * w);
    }
}

extern "C" void kernel_launch(void* const* d_in, const int* in_sizes, int n_in,
                              void* d_out, int out_size) {
    const float* x = (const float*)d_in[0];
    const void* ei = d_in[1];
    const float* W1 = (const float*)d_in[2];
    const float* b1 = (const float*)d_in[3];
    const float* W2 = (const float*)d_in[4];
    const float* b2 = (const float*)d_in[5];
    float* out = (float*)d_out;

    const int n = in_sizes[0] / F1;
    const int E = in_sizes[1] / 2;

    const int T = 256;
    // edge index: detect dtype, normalize to int32
    detect_kernel<<<1, 256>>>(ei, E, n);
    convert_kernel<<<(2 * E + T - 1) / T, T>>>(ei, E, n);

    // degrees -> dinv
    deg_init_kernel<<<(n + T - 1) / T, T>>>(n);
    deg_count_kernel<<<(E + T - 1) / T, T>>>(E);
    deg_rsqrt_kernel<<<(n + T - 1) / T, T>>>(n);

    // layer 1: g_h1 = x @ W1
    gemm_kernel<128, 8, false><<<(n + 63) / 64, 256>>>(x, W1, nullptr, n);
    // g_agg1 = D^-1/2 (A+I) D^-1/2 g_h1
    init1_kernel<<<(n * (F1 / 4) + T - 1) / T, T>>>(n);
    scatter_kernel<F1><<<(E * 32 + T - 1) / T, T>>>(nullptr, E);

    // layer 2: g_h2 = relu(g_agg1 + b1) @ W2  (bias+relu fused into A-load)
    gemm_kernel<64, 4, true><<<(n + 63) / 64, 256>>>(nullptr, W2, b1, n);
    // out = D^-1/2 (A+I) D^-1/2 g_h2 + b2
    init2_kernel<<<(n * (F2 / 4) + T - 1) / T, T>>>(b2, out, n);
    scatter_kernel<F2><<<(E * 32 + T - 1) / T, T>>>(out, E);
}

// round 6
// speedup vs baseline: 4.0572x; 4.0572x over previous
#include <cuda_runtime.h>

#define MAXN 100000
#define MAXE 600000
#define F1 128
#define F2 64

// Scratch: __device__ globals (allocation-free rule), referenced directly as symbols.
__device__ float g_h1[MAXN * F1];    // x @ W1
__device__ float g_agg1[MAXN * F1];  // aggregated layer-1 (pre-bias/relu)
__device__ float g_h2[MAXN * F2];    // relu(agg1+b1) @ W2
__device__ float g_dinv[MAXN];       // deg -> rsqrt(deg)
__device__ int   g_eidx[2 * MAXE];   // normalized int32 edge index [src | dst]
__device__ int   g_is32;             // != 0 if raw edge buffer is int32

// ---------------- vector reduction atomics (sm_90+) ----------------
__device__ __forceinline__ void red_add_v4(float* p, float a, float b, float c, float d) {
    asm volatile("red.global.add.v4.f32 [%0], {%1, %2, %3, %4};"
                 :: "l"(p), "f"(a), "f"(b), "f"(c), "f"(d) : "memory");
}
__device__ __forceinline__ void red_add_v2(float* p, float a, float b) {
    asm volatile("red.global.add.v2.f32 [%0], {%1, %2};"
                 :: "l"(p), "f"(a), "f"(b) : "memory");
}

// ---------------- edge dtype detection ----------------
// Multi-block scan of the buffer as int64 over [0, E) (safe under both layouts).
// True int64 data: all values in [0, n). int32 misread as int64: huge values.
__global__ void detect_zero_kernel() { g_is32 = 0; }

__global__ void detect_kernel(const void* __restrict__ ei_raw, int E, int n) {
    const long long* p = (const long long*)ei_raw;
    int lbad = 0;
    for (int i = blockIdx.x * blockDim.x + threadIdx.x; i < E; i += gridDim.x * blockDim.x) {
        long long v = p[i];
        if (v < 0 || v >= (long long)n) lbad = 1;
    }
    if (__syncthreads_or(lbad) && threadIdx.x == 0) atomicOr(&g_is32, 1);
}

// normalize edges to int32 + init dinv to 1.0 (self-loop) in one pass
__global__ void convert_kernel(const void* __restrict__ ei_raw, int E, int n) {
    int i = blockIdx.x * blockDim.x + threadIdx.x;
    if (i < n) g_dinv[i] = 1.0f;
    if (i >= 2 * E) return;
    int v;
    if (g_is32) v = ((const int*)ei_raw)[i];
    else        v = (int)((const long long*)ei_raw)[i];
    // defensive clamp: a bad index becomes wrong-answer signal, not a device trap
    v = v < 0 ? 0 : (v >= n ? n - 1 : v);
    g_eidx[i] = v;
}

// ---------------- degree / norm ----------------
__global__ void deg_count_kernel(int E) {
    int e = blockIdx.x * blockDim.x + threadIdx.x;
    if (e < E) atomicAdd(&g_dinv[g_eidx[E + e]], 1.0f);
}

__global__ void deg_rsqrt_kernel(int n) {
    int i = blockIdx.x * blockDim.x + threadIdx.x;
    if (i < n) g_dinv[i] = rsqrtf(g_dinv[i]);
}

// ---------------- GEMM ----------------
// LAYER2=false: C=g_h1, A=x (param),             no activation
// LAYER2=true : C=g_h2, A=g_agg1 (symbol), A-load fused with +b1,relu
template <int BN, int TN, bool LAYER2>
__global__ __launch_bounds__(256)
void gemm_kernel(const float* __restrict__ Ain, const float* __restrict__ W,
                 const float* __restrict__ bias, int M) {
    constexpr int BM = 64, BK = 32, K = 128;
    constexpr int TM = 4;
    constexpr int NTX = BN / TN;  // 16
    constexpr int NTY = BM / TM;  // 16
    static_assert(NTX * NTY == 256, "thread layout");

    __shared__ alignas(16) float As[BM][BK + 4];  // row stride 144B (16B multiple)
    __shared__ alignas(16) float Bs[BK][BN];
    __shared__ alignas(16) float bsh[K];

    const float* A = LAYER2 ? (const float*)g_agg1 : Ain;
    float* C = LAYER2 ? g_h2 : g_h1;

    const int tid = threadIdx.x;
    const int tx = tid % NTX;
    const int ty = tid / NTX;
    const int row0 = blockIdx.x * BM;

    if constexpr (LAYER2) {
        if (tid < K) bsh[tid] = bias[tid];
    }

    float acc[TM][TN];
#pragma unroll
    for (int m = 0; m < TM; m++)
#pragma unroll
        for (int j = 0; j < TN; j++) acc[m][j] = 0.0f;

    for (int k0 = 0; k0 < K; k0 += BK) {
        __syncthreads();
        // A tile: BM x BK = 2048 floats = 512 float4 (2 per thread)
#pragma unroll
        for (int i = 0; i < (BM * BK) / (256 * 4); i++) {
            int t = tid + i * 256;
            int r = t >> 3;   // / (BK/4)
            int c4 = t & 7;   // % (BK/4)
            float4 v = make_float4(0.f, 0.f, 0.f, 0.f);
            int grow = row0 + r;
            if (grow < M)
                v = *reinterpret_cast<const float4*>(&A[(size_t)grow * K + k0 + c4 * 4]);
            if constexpr (LAYER2) {
                int kk = k0 + c4 * 4;
                v.x = fmaxf(v.x + bsh[kk + 0], 0.f);
                v.y = fmaxf(v.y + bsh[kk + 1], 0.f);
                v.z = fmaxf(v.z + bsh[kk + 2], 0.f);
                v.w = fmaxf(v.w + bsh[kk + 3], 0.f);
            }
            *reinterpret_cast<float4*>(&As[r][c4 * 4]) = v;
        }
        // W tile: BK x BN
#pragma unroll
        for (int i = 0; i < (BK * BN) / (256 * 4); i++) {
            int t = tid + i * 256;
            int r = t / (BN / 4);
            int c4 = t % (BN / 4);
            *reinterpret_cast<float4*>(&Bs[r][c4 * 4]) =
                *reinterpret_cast<const float4*>(&W[(size_t)(k0 + r) * BN + c4 * 4]);
        }
        __syncthreads();

#pragma unroll
        for (int k = 0; k < BK; k++) {
            float a[TM];
#pragma unroll
            for (int m = 0; m < TM; m++) a[m] = As[ty * TM + m][k];
            float b[TN];
#pragma unroll
            for (int j = 0; j < TN; j += 4) {
                float4 bv = *reinterpret_cast<const float4*>(&Bs[k][tx * TN + j]);
                b[j] = bv.x; b[j + 1] = bv.y; b[j + 2] = bv.z; b[j + 3] = bv.w;
            }
#pragma unroll
            for (int m = 0; m < TM; m++)
#pragma unroll
                for (int j = 0; j < TN; j++)
                    acc[m][j] = fmaf(a[m], b[j], acc[m][j]);
        }
    }

#pragma unroll
    for (int m = 0; m < TM; m++) {
        int grow = row0 + ty * TM + m;
        if (grow < M) {
#pragma unroll
            for (int j = 0; j < TN; j += 4) {
                float4 v = make_float4(acc[m][j], acc[m][j + 1], acc[m][j + 2], acc[m][j + 3]);
                *reinterpret_cast<float4*>(&C[(size_t)grow * BN + tx * TN + j]) = v;
            }
        }
    }
}

// ---------------- aggregation ----------------
// layer1 self-loop init: g_agg1 = dinv^2 * g_h1
__global__ void init1_kernel(int n) {
    int idx = blockIdx.x * blockDim.x + threadIdx.x;
    int total = n * (F1 / 4);
    if (idx < total) {
        int i = idx / (F1 / 4);
        float di = g_dinv[i];
        float w = di * di;
        float4 v = reinterpret_cast<const float4*>(g_h1)[idx];
        v.x *= w; v.y *= w; v.z *= w; v.w *= w;
        reinterpret_cast<float4*>(g_agg1)[idx] = v;
    }
}

// layer2 self-loop init + bias: out = dinv^2 * g_h2 + b2 (writes d_out directly)
__global__ void init2_kernel(const float* __restrict__ b2, float* __restrict__ out, int n) {
    int idx = blockIdx.x * blockDim.x + threadIdx.x;
    int total = n * (F2 / 4);
    if (idx < total) {
        int i = idx / (F2 / 4);
        int c4 = idx % (F2 / 4);
        float di = g_dinv[i];
        float w = di * di;
        float4 v = reinterpret_cast<const float4*>(g_h2)[idx];
        float4 b = reinterpret_cast<const float4*>(b2)[c4];
        v.x = fmaf(v.x, w, b.x);
        v.y = fmaf(v.y, w, b.y);
        v.z = fmaf(v.z, w, b.z);
        v.w = fmaf(v.w, w, b.w);
        reinterpret_cast<float4*>(out)[idx] = v;
    }
}

// One warp per edge: gather src row, scale by dinv[s]*dinv[d], vector-RED into dst row.
// F==F1: h=g_h1, acc=g_agg1 (symbols). F==F2: h=g_h2, acc=outp (d_out).
template <int F>
__global__ void scatter_kernel(float* __restrict__ outp, int E) {
    int gw = (blockIdx.x * blockDim.x + threadIdx.x) >> 5;
    if (gw >= E) return;
    int lane = threadIdx.x & 31;
    int s = g_eidx[gw];
    int d = g_eidx[E + gw];
    float w = g_dinv[s] * g_dinv[d];
    const float* h = (F == F1) ? (const float*)g_h1 : (const float*)g_h2;
    float* acc = (F == F1) ? (float*)g_agg1 : outp;
    constexpr int PER = F / 32;  // 4 or 2
    const float* hs = h + (size_t)s * F + lane * PER;
    float* ad = acc + (size_t)d * F + lane * PER;
    if (PER == 4) {
        float4 v = *reinterpret_cast<const float4*>(hs);
        red_add_v4(ad, v.x * w, v.y * w, v.z * w, v.w * w);
    } else {
        float2 v = *reinterpret_cast<const float2*>(hs);
        red_add_v2(ad, v.x * w, v.y * w);
    }
}

extern "C" void kernel_launch(void* const* d_in, const int* in_sizes, int n_in,
                              void* d_out, int out_size) {
    const float* x = (const float*)d_in[0];
    const void* ei = d_in[1];
    const float* W1 = (const float*)d_in[2];
    const float* b1 = (const float*)d_in[3];
    const float* W2 = (const float*)d_in[4];
    const float* b2 = (const float*)d_in[5];
    float* out = (float*)d_out;

    const int n = in_sizes[0] / F1;
    const int E = in_sizes[1] / 2;

    const int T = 256;
    // edge index: detect dtype, normalize to int32 (+ dinv self-loop init fused)
    detect_zero_kernel<<<1, 1>>>();
    detect_kernel<<<256, T>>>(ei, E, n);
    convert_kernel<<<(2 * E + T - 1) / T, T>>>(ei, E, n);

    // degrees -> dinv
    deg_count_kernel<<<(E + T - 1) / T, T>>>(E);
    deg_rsqrt_kernel<<<(n + T - 1) / T, T>>>(n);

    // layer 1: g_h1 = x @ W1
    gemm_kernel<128, 8, false><<<(n + 63) / 64, 256>>>(x, W1, nullptr, n);
    // g_agg1 = D^-1/2 (A+I) D^-1/2 g_h1
    init1_kernel<<<(n * (F1 / 4) + T - 1) / T, T>>>(n);
    scatter_kernel<F1><<<(E * 32 + T - 1) / T, T>>>(nullptr, E);

    // layer 2: g_h2 = relu(g_agg1 + b1) @ W2  (bias+relu fused into A-load)
    gemm_kernel<64, 4, true><<<(n + 63) / 64, 256>>>(nullptr, W2, b1, n);
    // out = D^-1/2 (A+I) D^-1/2 g_h2 + b2
    init2_kernel<<<(n * (F2 / 4) + T - 1) / T, T>>>(b2, out, n);
    scatter_kernel<F2><<<(E * 32 + T - 1) / T, T>>>(out, E);
}

// round 7
// speedup vs baseline: 6.0655x; 1.4950x over previous
#include <cuda_runtime.h>
#include <cstdint>

#define MAXN 100000
#define MAXE 600000
#define F1 128
#define F2 64

// Scratch: __device__ globals (allocation-free rule), referenced directly as symbols.
__device__ float g_h1[MAXN * F1];    // x @ W1
__device__ float g_agg1[MAXN * F1];  // aggregated layer-1 (pre-bias/relu)
__device__ float g_h2[MAXN * F2];    // relu(agg1+b1) @ W2
__device__ float g_dinv[MAXN];       // deg -> rsqrt(deg)
__device__ int   g_eidx[2 * MAXE];   // normalized int32 edge index [src | dst]
__device__ int   g_is32;             // != 0 if raw edge buffer is int32

// ---------------- vector reduction atomics (sm_90+) ----------------
__device__ __forceinline__ void red_add_v4(float* p, float a, float b, float c, float d) {
    asm volatile("red.global.add.v4.f32 [%0], {%1, %2, %3, %4};"
                 :: "l"(p), "f"(a), "f"(b), "f"(c), "f"(d) : "memory");
}
__device__ __forceinline__ void red_add_v2(float* p, float a, float b) {
    asm volatile("red.global.add.v2.f32 [%0], {%1, %2};"
                 :: "l"(p), "f"(a), "f"(b) : "memory");
}

// ---------------- tf32 helpers ----------------
__device__ __forceinline__ uint32_t f2tf(float f) {
    uint32_t u;
    asm("cvt.rna.tf32.f32 %0, %1;" : "=r"(u) : "f"(f));
    return u;
}
__device__ __forceinline__ void mma_tf32(float* c, uint32_t a0, uint32_t a1, uint32_t a2,
                                         uint32_t a3, uint32_t b0, uint32_t b1) {
    asm volatile(
        "mma.sync.aligned.m16n8k8.row.col.f32.tf32.tf32.f32 "
        "{%0,%1,%2,%3}, {%4,%5,%6,%7}, {%8,%9}, {%0,%1,%2,%3};"
        : "+f"(c[0]), "+f"(c[1]), "+f"(c[2]), "+f"(c[3])
        : "r"(a0), "r"(a1), "r"(a2), "r"(a3), "r"(b0), "r"(b1));
}

// ---------------- edge dtype detection ----------------
__global__ void detect_zero_kernel() { g_is32 = 0; }

__global__ void detect_kernel(const void* __restrict__ ei_raw, int E, int n) {
    const long long* p = (const long long*)ei_raw;
    int lbad = 0;
    for (int i = blockIdx.x * blockDim.x + threadIdx.x; i < E; i += gridDim.x * blockDim.x) {
        long long v = p[i];
        if (v < 0 || v >= (long long)n) lbad = 1;
    }
    if (__syncthreads_or(lbad) && threadIdx.x == 0) atomicOr(&g_is32, 1);
}

// normalize edges to int32 + init dinv to 1.0 (self-loop) in one pass
__global__ void convert_kernel(const void* __restrict__ ei_raw, int E, int n) {
    int i = blockIdx.x * blockDim.x + threadIdx.x;
    if (i < n) g_dinv[i] = 1.0f;
    if (i >= 2 * E) return;
    int v;
    if (g_is32) v = ((const int*)ei_raw)[i];
    else        v = (int)((const long long*)ei_raw)[i];
    v = v < 0 ? 0 : (v >= n ? n - 1 : v);
    g_eidx[i] = v;
}

// ---------------- degree / norm ----------------
__global__ void deg_count_kernel(int E) {
    int e = blockIdx.x * blockDim.x + threadIdx.x;
    if (e < E) atomicAdd(&g_dinv[g_eidx[E + e]], 1.0f);
}

__global__ void deg_rsqrt_kernel(int n) {
    int i = blockIdx.x * blockDim.x + threadIdx.x;
    if (i < n) g_dinv[i] = rsqrtf(g_dinv[i]);
}

// ---------------- TF32 tensor-core GEMM ----------------
// C[M,N] = act(A[M,128]) @ W[128,N]
// LAYER2=false: A=Ain (x), C=g_h1, no activation
// LAYER2=true : A=g_agg1 (symbol), C=g_h2, A-load fused with +b1,relu
// Block tile: 128 rows x N cols. 8 warps, warp w owns rows [w*16, w*16+16).
// mma.m16n8k8 tf32, fp32 accumulate. BK=32 k-chunks (4 k8 steps each).
template <int N, bool LAYER2>
__global__ __launch_bounds__(256)
void mma_gemm_kernel(const float* __restrict__ Ain, const float* __restrict__ W,
                     const float* __restrict__ bias, int M) {
    constexpr int K = 128, BM = 128, BK = 32;
    constexpr int ASTR = 36;     // A row stride (words): (4*gid+tig)%32 distinct -> conflict-free
    constexpr int WSTR = N + 8;  // W row stride (words): (8*tig+gid)%32 distinct -> conflict-free
    constexpr int NT = N / 8;    // n-tiles per warp

    __shared__ alignas(16) uint32_t As[BM][ASTR];
    __shared__ alignas(16) uint32_t Ws[BK][WSTR];
    __shared__ alignas(16) float bsh[K];

    const float* A = LAYER2 ? (const float*)g_agg1 : Ain;
    float* C = LAYER2 ? g_h2 : g_h1;

    const int tid = threadIdx.x;
    const int warp = tid >> 5;
    const int lane = tid & 31;
    const int gid = lane >> 2;   // group row (0-7)
    const int tig = lane & 3;    // thread-in-group (0-3)
    const int row0 = blockIdx.x * BM;

    if (LAYER2) {
        if (tid < K) bsh[tid] = bias[tid];
        __syncthreads();
    }

    float acc[NT][4];
#pragma unroll
    for (int nt = 0; nt < NT; nt++)
#pragma unroll
        for (int j = 0; j < 4; j++) acc[nt][j] = 0.0f;

    for (int k0 = 0; k0 < K; k0 += BK) {
        // A tile: BM x BK = 4096 floats = 1024 float4 (4 per thread)
#pragma unroll
        for (int i = 0; i < 4; i++) {
            int t = tid + i * 256;
            int r = t >> 3;   // / (BK/4)
            int c4 = t & 7;   // % (BK/4)
            int grow = row0 + r;
            float4 v = make_float4(0.f, 0.f, 0.f, 0.f);
            if (grow < M)
                v = *reinterpret_cast<const float4*>(&A[(size_t)grow * K + k0 + c4 * 4]);
            if constexpr (LAYER2) {
                int kk = k0 + c4 * 4;
                v.x = fmaxf(v.x + bsh[kk + 0], 0.f);
                v.y = fmaxf(v.y + bsh[kk + 1], 0.f);
                v.z = fmaxf(v.z + bsh[kk + 2], 0.f);
                v.w = fmaxf(v.w + bsh[kk + 3], 0.f);
            }
            uint4 u = make_uint4(f2tf(v.x), f2tf(v.y), f2tf(v.z), f2tf(v.w));
            *reinterpret_cast<uint4*>(&As[r][c4 * 4]) = u;
        }
        // W tile: BK x N floats
#pragma unroll
        for (int i = 0; i < (BK * N) / (256 * 4); i++) {
            int t = tid + i * 256;
            int r = t / (N / 4);
            int c4 = t % (N / 4);
            float4 v = *reinterpret_cast<const float4*>(&W[(size_t)(k0 + r) * N + c4 * 4]);
            uint4 u = make_uint4(f2tf(v.x), f2tf(v.y), f2tf(v.z), f2tf(v.w));
            *reinterpret_cast<uint4*>(&Ws[r][c4 * 4]) = u;
        }
        __syncthreads();

#pragma unroll
        for (int ks = 0; ks < BK / 8; ks++) {
            int kk = ks * 8;
            uint32_t a0 = As[warp * 16 + gid][kk + tig];
            uint32_t a1 = As[warp * 16 + gid + 8][kk + tig];
            uint32_t a2 = As[warp * 16 + gid][kk + tig + 4];
            uint32_t a3 = As[warp * 16 + gid + 8][kk + tig + 4];
#pragma unroll
            for (int nt = 0; nt < NT; nt++) {
                uint32_t b0 = Ws[kk + tig][nt * 8 + gid];
                uint32_t b1 = Ws[kk + tig + 4][nt * 8 + gid];
                mma_tf32(acc[nt], a0, a1, a2, a3, b0, b1);
            }
        }
        __syncthreads();
    }

    // store: c0,c1 -> (row gid, cols tig*2, tig*2+1); c2,c3 -> row gid+8
    int r0 = row0 + warp * 16 + gid;
    int r1 = r0 + 8;
#pragma unroll
    for (int nt = 0; nt < NT; nt++) {
        int col = nt * 8 + tig * 2;
        if (r0 < M)
            *reinterpret_cast<float2*>(&C[(size_t)r0 * N + col]) =
                make_float2(acc[nt][0], acc[nt][1]);
        if (r1 < M)
            *reinterpret_cast<float2*>(&C[(size_t)r1 * N + col]) =
                make_float2(acc[nt][2], acc[nt][3]);
    }
}

// ---------------- aggregation ----------------
// layer1 self-loop init: g_agg1 = dinv^2 * g_h1
__global__ void init1_kernel(int n) {
    int idx = blockIdx.x * blockDim.x + threadIdx.x;
    int total = n * (F1 / 4);
    if (idx < total) {
        int i = idx / (F1 / 4);
        float di = g_dinv[i];
        float w = di * di;
        float4 v = reinterpret_cast<const float4*>(g_h1)[idx];
        v.x *= w; v.y *= w; v.z *= w; v.w *= w;
        reinterpret_cast<float4*>(g_agg1)[idx] = v;
    }
}

// layer2 self-loop init + bias: out = dinv^2 * g_h2 + b2 (writes d_out directly)
__global__ void init2_kernel(const float* __restrict__ b2, float* __restrict__ out, int n) {
    int idx = blockIdx.x * blockDim.x + threadIdx.x;
    int total = n * (F2 / 4);
    if (idx < total) {
        int i = idx / (F2 / 4);
        int c4 = idx % (F2 / 4);
        float di = g_dinv[i];
        float w = di * di;
        float4 v = reinterpret_cast<const float4*>(g_h2)[idx];
        float4 b = reinterpret_cast<const float4*>(b2)[c4];
        v.x = fmaf(v.x, w, b.x);
        v.y = fmaf(v.y, w, b.y);
        v.z = fmaf(v.z, w, b.z);
        v.w = fmaf(v.w, w, b.w);
        reinterpret_cast<float4*>(out)[idx] = v;
    }
}

// One warp per edge: gather src row, scale by dinv[s]*dinv[d], vector-RED into dst row.
template <int F>
__global__ void scatter_kernel(float* __restrict__ outp, int E) {
    int gw = (blockIdx.x * blockDim.x + threadIdx.x) >> 5;
    if (gw >= E) return;
    int lane = threadIdx.x & 31;
    int s = g_eidx[gw];
    int d = g_eidx[E + gw];
    float w = g_dinv[s] * g_dinv[d];
    const float* h = (F == F1) ? (const float*)g_h1 : (const float*)g_h2;
    float* acc = (F == F1) ? (float*)g_agg1 : outp;
    constexpr int PER = F / 32;  // 4 or 2
    const float* hs = h + (size_t)s * F + lane * PER;
    float* ad = acc + (size_t)d * F + lane * PER;
    if (PER == 4) {
        float4 v = *reinterpret_cast<const float4*>(hs);
        red_add_v4(ad, v.x * w, v.y * w, v.z * w, v.w * w);
    } else {
        float2 v = *reinterpret_cast<const float2*>(hs);
        red_add_v2(ad, v.x * w, v.y * w);
    }
}

extern "C" void kernel_launch(void* const* d_in, const int* in_sizes, int n_in,
                              void* d_out, int out_size) {
    const float* x = (const float*)d_in[0];
    const void* ei = d_in[1];
    const float* W1 = (const float*)d_in[2];
    const float* b1 = (const float*)d_in[3];
    const float* W2 = (const float*)d_in[4];
    const float* b2 = (const float*)d_in[5];
    float* out = (float*)d_out;

    const int n = in_sizes[0] / F1;
    const int E = in_sizes[1] / 2;

    const int T = 256;
    // edge index: detect dtype, normalize to int32 (+ dinv self-loop init fused)
    detect_zero_kernel<<<1, 1>>>();
    detect_kernel<<<256, T>>>(ei, E, n);
    convert_kernel<<<(2 * E + T - 1) / T, T>>>(ei, E, n);

    // degrees -> dinv
    deg_count_kernel<<<(E + T - 1) / T, T>>>(E);
    deg_rsqrt_kernel<<<(n + T - 1) / T, T>>>(n);

    // layer 1: g_h1 = x @ W1  (tf32 tensor cores)
    mma_gemm_kernel<128, false><<<(n + 127) / 128, 256>>>(x, W1, nullptr, n);
    // g_agg1 = D^-1/2 (A+I) D^-1/2 g_h1
    init1_kernel<<<(n * (F1 / 4) + T - 1) / T, T>>>(n);
    scatter_kernel<F1><<<(E * 32 + T - 1) / T, T>>>(nullptr, E);

    // layer 2: g_h2 = relu(g_agg1 + b1) @ W2  (bias+relu fused into A-load)
    mma_gemm_kernel<64, true><<<(n + 127) / 128, 256>>>(nullptr, W2, b1, n);
    // out = D^-1/2 (A+I) D^-1/2 g_h2 + b2
    init2_kernel<<<(n * (F2 / 4) + T - 1) / T, T>>>(b2, out, n);
    scatter_kernel<F2><<<(E * 32 + T - 1) / T, T>>>(out, E);
}

// round 9
// speedup vs baseline: 8.0317x; 1.3242x over previous
#include <cuda_runtime.h>
#include <cstdint>

#define MAXN 100000
#define MAXE 600000
#define F1 128
#define F2 64
#define SCAN_T 256

// Scratch: __device__ globals (allocation-free rule), referenced directly as symbols.
__device__ float g_h1[MAXN * F1];     // x @ W1
__device__ float g_agg1[MAXN * F1];   // aggregated layer-1 (pre-bias/relu)
__device__ float g_h2[MAXN * F2];     // relu(agg1+b1) @ W2
__device__ float g_dinv[MAXN];        // rsqrt(deg+1)
__device__ int   g_eidx[2 * MAXE];    // normalized int32 edge index [src | dst]
__device__ int   g_is32;              // != 0 if raw edge buffer is int32
__device__ int   g_deg[MAXN];         // in-degree (excl self-loop)
__device__ int   g_rowptr[MAXN + 1];  // CSR row pointers (by dst)
__device__ int   g_cnt[MAXN];         // fill counters
__device__ int   g_col[MAXE];         // CSR: src per edge
__device__ float g_wsrc[MAXE];        // CSR: dinv[src] per edge
__device__ int   g_bsum[1024];        // block sums for scan

// ---------------- tf32 helpers ----------------
__device__ __forceinline__ uint32_t f2tf(float f) {
    uint32_t u;
    asm("cvt.rna.tf32.f32 %0, %1;" : "=r"(u) : "f"(f));
    return u;
}
__device__ __forceinline__ void mma_tf32(float* c, uint32_t a0, uint32_t a1, uint32_t a2,
                                         uint32_t a3, uint32_t b0, uint32_t b1) {
    asm volatile(
        "mma.sync.aligned.m16n8k8.row.col.f32.tf32.tf32.f32 "
        "{%0,%1,%2,%3}, {%4,%5,%6,%7}, {%8,%9}, {%0,%1,%2,%3};"
        : "+f"(c[0]), "+f"(c[1]), "+f"(c[2]), "+f"(c[3])
        : "r"(a0), "r"(a1), "r"(a2), "r"(a3), "r"(b0), "r"(b1));
}

// ---------------- edge dtype detection ----------------
__global__ void detect_zero_kernel() { g_is32 = 0; }

__global__ void detect_kernel(const void* __restrict__ ei_raw, int E, int n) {
    const long long* p = (const long long*)ei_raw;
    int lbad = 0;
    for (int i = blockIdx.x * blockDim.x + threadIdx.x; i < E; i += gridDim.x * blockDim.x) {
        long long v = p[i];
        if (v < 0 || v >= (long long)n) lbad = 1;
    }
    if (__syncthreads_or(lbad) && threadIdx.x == 0) atomicOr(&g_is32, 1);
}

// normalize edges to int32 + zero degree histogram in one pass
__global__ void convert_kernel(const void* __restrict__ ei_raw, int E, int n) {
    int i = blockIdx.x * blockDim.x + threadIdx.x;
    if (i < n) g_deg[i] = 0;
    if (i >= 2 * E) return;
    int v;
    if (g_is32) v = ((const int*)ei_raw)[i];
    else        v = (int)((const long long*)ei_raw)[i];
    v = v < 0 ? 0 : (v >= n ? n - 1 : v);
    g_eidx[i] = v;
}

// ---------------- CSR build ----------------
__global__ void deg_count_kernel(int E) {
    int e = blockIdx.x * blockDim.x + threadIdx.x;
    if (e < E) atomicAdd(&g_deg[g_eidx[E + e]], 1);
}

// pass 1: per-block exclusive scan of g_deg -> g_rowptr (local), block sums -> g_bsum
__global__ void scan1_kernel(int n) {
    __shared__ int sh[SCAN_T];
    int i = blockIdx.x * SCAN_T + threadIdx.x;
    int v = (i < n) ? g_deg[i] : 0;
    sh[threadIdx.x] = v;
    __syncthreads();
    int acc = v;
#pragma unroll
    for (int off = 1; off < SCAN_T; off <<= 1) {
        int t = (threadIdx.x >= off) ? sh[threadIdx.x - off] : 0;
        __syncthreads();
        acc += t;
        sh[threadIdx.x] = acc;
        __syncthreads();
    }
    if (i < n) g_rowptr[i] = acc - v;  // exclusive
    if (threadIdx.x == SCAN_T - 1) g_bsum[blockIdx.x] = acc;
}

// pass 2: single block exclusive scan of block sums (nb <= 1024)
__global__ void scan2_kernel(int nb) {
    __shared__ int sh[1024];
    int v = (threadIdx.x < nb) ? g_bsum[threadIdx.x] : 0;
    sh[threadIdx.x] = v;
    __syncthreads();
    int acc = v;
#pragma unroll
    for (int off = 1; off < 1024; off <<= 1) {
        int t = (threadIdx.x >= off) ? sh[threadIdx.x - off] : 0;
        __syncthreads();
        acc += t;
        sh[threadIdx.x] = acc;
        __syncthreads();
    }
    if (threadIdx.x < nb) g_bsum[threadIdx.x] = acc - v;  // exclusive
}

// pass 3: add block offsets; compute dinv = rsqrt(deg+1); zero fill counters; rowptr[n]=E
__global__ void scan3_kernel(int n, int E) {
    int i = blockIdx.x * blockDim.x + threadIdx.x;
    if (i < n) {
        g_rowptr[i] += g_bsum[i / SCAN_T];
        g_dinv[i] = rsqrtf((float)(g_deg[i] + 1));
        g_cnt[i] = 0;
    }
    if (i == 0) g_rowptr[n] = E;
}

// fill CSR buckets: col = src, wsrc = dinv[src]
__global__ void fill_kernel(int E) {
    int e = blockIdx.x * blockDim.x + threadIdx.x;
    if (e >= E) return;
    int s = g_eidx[e];
    int d = g_eidx[E + e];
    int pos = g_rowptr[d] + atomicAdd(&g_cnt[d], 1);
    g_col[pos] = s;
    g_wsrc[pos] = g_dinv[s];
}

// ---------------- TF32 tensor-core GEMM ----------------
// C[M,N] = act(A[M,128]) @ W[128,N]
// LAYER2=false: A=Ain (x), C=g_h1, no activation
// LAYER2=true : A=g_agg1 (symbol), C=g_h2, A-load fused with +b1,relu
template <int N, bool LAYER2>
__global__ __launch_bounds__(256)
void mma_gemm_kernel(const float* __restrict__ Ain, const float* __restrict__ W,
                     const float* __restrict__ bias, int M) {
    constexpr int K = 128, BM = 128, BK = 32;
    constexpr int ASTR = 36;
    constexpr int WSTR = N + 8;
    constexpr int NT = N / 8;

    __shared__ alignas(16) uint32_t As[BM][ASTR];
    __shared__ alignas(16) uint32_t Ws[BK][WSTR];
    __shared__ alignas(16) float bsh[K];

    const float* A = LAYER2 ? (const float*)g_agg1 : Ain;
    float* C = LAYER2 ? g_h2 : g_h1;

    const int tid = threadIdx.x;
    const int warp = tid >> 5;
    const int lane = tid & 31;
    const int gid = lane >> 2;
    const int tig = lane & 3;
    const int row0 = blockIdx.x * BM;

    if (LAYER2) {
        if (tid < K) bsh[tid] = bias[tid];
        __syncthreads();
    }

    float acc[NT][4];
#pragma unroll
    for (int nt = 0; nt < NT; nt++)
#pragma unroll
        for (int j = 0; j < 4; j++) acc[nt][j] = 0.0f;

    for (int k0 = 0; k0 < K; k0 += BK) {
#pragma unroll
        for (int i = 0; i < 4; i++) {
            int t = tid + i * 256;
            int r = t >> 3;
            int c4 = t & 7;
            int grow = row0 + r;
            float4 v = make_float4(0.f, 0.f, 0.f, 0.f);
            if (grow < M)
                v = *reinterpret_cast<const float4*>(&A[(size_t)grow * K + k0 + c4 * 4]);
            if constexpr (LAYER2) {
                int kk = k0 + c4 * 4;
                v.x = fmaxf(v.x + bsh[kk + 0], 0.f);
                v.y = fmaxf(v.y + bsh[kk + 1], 0.f);
                v.z = fmaxf(v.z + bsh[kk + 2], 0.f);
                v.w = fmaxf(v.w + bsh[kk + 3], 0.f);
            }
            uint4 u = make_uint4(f2tf(v.x), f2tf(v.y), f2tf(v.z), f2tf(v.w));
            *reinterpret_cast<uint4*>(&As[r][c4 * 4]) = u;
        }
#pragma unroll
        for (int i = 0; i < (BK * N) / (256 * 4); i++) {
            int t = tid + i * 256;
            int r = t / (N / 4);
            int c4 = t % (N / 4);
            float4 v = *reinterpret_cast<const float4*>(&W[(size_t)(k0 + r) * N + c4 * 4]);
            uint4 u = make_uint4(f2tf(v.x), f2tf(v.y), f2tf(v.z), f2tf(v.w));
            *reinterpret_cast<uint4*>(&Ws[r][c4 * 4]) = u;
        }
        __syncthreads();

#pragma unroll
        for (int ks = 0; ks < BK / 8; ks++) {
            int kk = ks * 8;
            uint32_t a0 = As[warp * 16 + gid][kk + tig];
            uint32_t a1 = As[warp * 16 + gid + 8][kk + tig];
            uint32_t a2 = As[warp * 16 + gid][kk + tig + 4];
            uint32_t a3 = As[warp * 16 + gid + 8][kk + tig + 4];
#pragma unroll
            for (int nt = 0; nt < NT; nt++) {
                uint32_t b0 = Ws[kk + tig][nt * 8 + gid];
                uint32_t b1 = Ws[kk + tig + 4][nt * 8 + gid];
                mma_tf32(acc[nt], a0, a1, a2, a3, b0, b1);
            }
        }
        __syncthreads();
    }

    int r0 = row0 + warp * 16 + gid;
    int r1 = r0 + 8;
#pragma unroll
    for (int nt = 0; nt < NT; nt++) {
        int col = nt * 8 + tig * 2;
        if (r0 < M)
            *reinterpret_cast<float2*>(&C[(size_t)r0 * N + col]) =
                make_float2(acc[nt][0], acc[nt][1]);
        if (r1 < M)
            *reinterpret_cast<float2*>(&C[(size_t)r1 * N + col]) =
                make_float2(acc[nt][2], acc[nt][3]);
    }
}

// ---------------- CSR gather aggregation ----------------
// One warp per dst node d:
//   acc = sum_{e in [rowptr[d],rowptr[d+1])} wsrc[e] * h[col[e]]
//   out[d] = dinv[d]*acc + dinv[d]^2*h[d] (+ b2 for layer 2)
// F==F1: h=g_h1, out=g_agg1 (raw, pre-bias/relu: GEMM2 fuses those).
// F==F2: h=g_h2, out=outp (d_out), + b2.
template <int F>
__global__ void gather_kernel(const float* __restrict__ b2, float* __restrict__ outp, int n) {
    int d = (blockIdx.x * blockDim.x + threadIdx.x) >> 5;
    if (d >= n) return;
    int lane = threadIdx.x & 31;
    const float* h = (F == F1) ? (const float*)g_h1 : (const float*)g_h2;
    float* outb = (F == F1) ? (float*)g_agg1 : outp;
    constexpr int PER = F / 32;  // 4 or 2

    int beg = g_rowptr[d];
    int end = g_rowptr[d + 1];
    float di = g_dinv[d];

    float a0 = 0.f, a1 = 0.f, a2 = 0.f, a3 = 0.f;
    for (int base = beg; base < end; base += 32) {
        int idx = 0; float w = 0.f;
        int m = end - base;
        if (lane < m) { idx = g_col[base + lane]; w = g_wsrc[base + lane]; }
        int cnt = m < 32 ? m : 32;
        for (int j = 0; j < cnt; j++) {
            int s = __shfl_sync(0xffffffffu, idx, j);
            float ww = __shfl_sync(0xffffffffu, w, j);
            const float* hs = h + (size_t)s * F + lane * PER;
            if (PER == 4) {
                float4 v = *reinterpret_cast<const float4*>(hs);
                a0 = fmaf(ww, v.x, a0); a1 = fmaf(ww, v.y, a1);
                a2 = fmaf(ww, v.z, a2); a3 = fmaf(ww, v.w, a3);
            } else {
                float2 v = *reinterpret_cast<const float2*>(hs);
                a0 = fmaf(ww, v.x, a0); a1 = fmaf(ww, v.y, a1);
            }
        }
    }

    // self-loop + scale (+ bias for layer 2)
    const float* hd = h + (size_t)d * F + lane * PER;
    float* od = outb + (size_t)d * F + lane * PER;
    if (PER == 4) {
        float4 v = *reinterpret_cast<const float4*>(hd);
        float4 r;
        r.x = di * fmaf(di, v.x, a0);
        r.y = di * fmaf(di, v.y, a1);
        r.z = di * fmaf(di, v.z, a2);
        r.w = di * fmaf(di, v.w, a3);
        *reinterpret_cast<float4*>(od) = r;
    } else {
        float2 v = *reinterpret_cast<const float2*>(hd);
        float2 b = *reinterpret_cast<const float2*>(&b2[lane * PER]);
        float2 r;
        r.x = di * fmaf(di, v.x, a0) + b.x;
        r.y = di * fmaf(di, v.y, a1) + b.y;
        *reinterpret_cast<float2*>(od) = r;
    }
}

extern "C" void kernel_launch(void* const* d_in, const int* in_sizes, int n_in,
                              void* d_out, int out_size) {
    const float* x = (const float*)d_in[0];
    const void* ei = d_in[1];
    const float* W1 = (const float*)d_in[2];
    const float* b1 = (const float*)d_in[3];
    const float* W2 = (const float*)d_in[4];
    const float* b2 = (const float*)d_in[5];
    float* out = (float*)d_out;

    const int n = in_sizes[0] / F1;
    const int E = in_sizes[1] / 2;

    const int T = 256;
    // edge index: detect dtype, normalize to int32 (+ degree zeroing fused)
    detect_zero_kernel<<<1, 1>>>();
    detect_kernel<<<256, T>>>(ei, E, n);
    convert_kernel<<<(2 * E + T - 1) / T, T>>>(ei, E, n);

    // CSR build: degree -> exclusive scan -> dinv -> bucket fill
    deg_count_kernel<<<(E + T - 1) / T, T>>>(E);
    int nb = (n + SCAN_T - 1) / SCAN_T;
    scan1_kernel<<<nb, SCAN_T>>>(n);
    scan2_kernel<<<1, 1024>>>(nb);
    scan3_kernel<<<(n + T - 1) / T, T>>>(n, E);
    fill_kernel<<<(E + T - 1) / T, T>>>(E);

    // layer 1: g_h1 = x @ W1  (tf32 tensor cores)
    mma_gemm_kernel<128, false><<<(n + 127) / 128, 256>>>(x, W1, nullptr, n);
    // g_agg1 = D^-1/2 (A+I) D^-1/2 g_h1   (CSR gather, no atomics)
    gather_kernel<F1><<<(n * 32 + T - 1) / T, T>>>(nullptr, nullptr, n);

    // layer 2: g_h2 = relu(g_agg1 + b1) @ W2  (bias+relu fused into A-load)
    mma_gemm_kernel<64, true><<<(n + 127) / 128, 256>>>(nullptr, W2, b1, n);
    // out = D^-1/2 (A+I) D^-1/2 g_h2 + b2   (CSR gather, writes d_out)
    gather_kernel<F2><<<(n * 32 + T - 1) / T, T>>>(b2, out, n);
}

// round 10
// speedup vs baseline: 9.0682x; 1.1290x over previous
#include <cuda_runtime.h>
#include <cuda_fp16.h>
#include <cstdint>

#define MAXN 100000
#define MAXE 600000
#define F1 128
#define F2 64
#define SCAN_T 256

// Scratch: __device__ globals (allocation-free rule), referenced directly as symbols.
__device__ __half g_h1h[MAXN * F1];   // x @ W1 (fp16, gather operand)
__device__ float  g_agg1[MAXN * F1];  // aggregated layer-1 (fp32, pre-bias/relu)
__device__ __half g_h2h[MAXN * F2];   // relu(agg1+b1) @ W2 (fp16, gather operand)
__device__ float  g_dinv[MAXN];       // rsqrt(deg+1)
__device__ int    g_eidx[2 * MAXE];   // normalized int32 edge index [src | dst]
__device__ int    g_is32;             // != 0 if raw edge buffer is int32
__device__ int    g_deg[MAXN];        // in-degree (excl self-loop)
__device__ int    g_rowptr[MAXN + 1]; // CSR row pointers (by dst)
__device__ int    g_cnt[MAXN];        // fill counters
__device__ int    g_col[MAXE];        // CSR: src per edge
__device__ float  g_wsrc[MAXE];       // CSR: dinv[src] per edge
__device__ int    g_bsum[1024];       // block sums for scan

// ---------------- tf32 helpers ----------------
__device__ __forceinline__ uint32_t f2tf(float f) {
    uint32_t u;
    asm("cvt.rna.tf32.f32 %0, %1;" : "=r"(u) : "f"(f));
    return u;
}
__device__ __forceinline__ void mma_tf32(float* c, uint32_t a0, uint32_t a1, uint32_t a2,
                                         uint32_t a3, uint32_t b0, uint32_t b1) {
    asm volatile(
        "mma.sync.aligned.m16n8k8.row.col.f32.tf32.tf32.f32 "
        "{%0,%1,%2,%3}, {%4,%5,%6,%7}, {%8,%9}, {%0,%1,%2,%3};"
        : "+f"(c[0]), "+f"(c[1]), "+f"(c[2]), "+f"(c[3])
        : "r"(a0), "r"(a1), "r"(a2), "r"(a3), "r"(b0), "r"(b1));
}

// ---------------- edge dtype detection (+ zero degree histogram) ----------------
__global__ void detect_zero_kernel() { g_is32 = 0; }

__global__ void detect_kernel(const void* __restrict__ ei_raw, int E, int n) {
    const long long* p = (const long long*)ei_raw;
    int lbad = 0;
    for (int i = blockIdx.x * blockDim.x + threadIdx.x; i < E; i += gridDim.x * blockDim.x) {
        long long v = p[i];
        if (v < 0 || v >= (long long)n) lbad = 1;
    }
    // zero degree histogram in the same pass (runs before convert)
    for (int i = blockIdx.x * blockDim.x + threadIdx.x; i < n; i += gridDim.x * blockDim.x)
        g_deg[i] = 0;
    if (__syncthreads_or(lbad) && threadIdx.x == 0) atomicOr(&g_is32, 1);
}

// normalize edges to int32 + count in-degrees (dst half) in one pass
__global__ void convert_kernel(const void* __restrict__ ei_raw, int E, int n) {
    int i = blockIdx.x * blockDim.x + threadIdx.x;
    if (i >= 2 * E) return;
    int v;
    if (g_is32) v = ((const int*)ei_raw)[i];
    else        v = (int)((const long long*)ei_raw)[i];
    v = v < 0 ? 0 : (v >= n ? n - 1 : v);
    g_eidx[i] = v;
    if (i >= E) atomicAdd(&g_deg[v], 1);  // dst half
}

// ---------------- CSR build ----------------
// pass 1: per-block exclusive scan of g_deg -> g_rowptr (local), block sums -> g_bsum
__global__ void scan1_kernel(int n) {
    __shared__ int sh[SCAN_T];
    int i = blockIdx.x * SCAN_T + threadIdx.x;
    int v = (i < n) ? g_deg[i] : 0;
    sh[threadIdx.x] = v;
    __syncthreads();
    int acc = v;
#pragma unroll
    for (int off = 1; off < SCAN_T; off <<= 1) {
        int t = (threadIdx.x >= off) ? sh[threadIdx.x - off] : 0;
        __syncthreads();
        acc += t;
        sh[threadIdx.x] = acc;
        __syncthreads();
    }
    if (i < n) g_rowptr[i] = acc - v;  // exclusive
    if (threadIdx.x == SCAN_T - 1) g_bsum[blockIdx.x] = acc;
}

// pass 2: single block exclusive scan of block sums (nb <= 1024)
__global__ void scan2_kernel(int nb) {
    __shared__ int sh[1024];
    int v = (threadIdx.x < nb) ? g_bsum[threadIdx.x] : 0;
    sh[threadIdx.x] = v;
    __syncthreads();
    int acc = v;
#pragma unroll
    for (int off = 1; off < 1024; off <<= 1) {
        int t = (threadIdx.x >= off) ? sh[threadIdx.x - off] : 0;
        __syncthreads();
        acc += t;
        sh[threadIdx.x] = acc;
        __syncthreads();
    }
    if (threadIdx.x < nb) g_bsum[threadIdx.x] = acc - v;  // exclusive
}

// pass 3: add block offsets; dinv = rsqrt(deg+1); zero fill counters; rowptr[n]=E
__global__ void scan3_kernel(int n, int E) {
    int i = blockIdx.x * blockDim.x + threadIdx.x;
    if (i < n) {
        g_rowptr[i] += g_bsum[i / SCAN_T];
        g_dinv[i] = rsqrtf((float)(g_deg[i] + 1));
        g_cnt[i] = 0;
    }
    if (i == 0) g_rowptr[n] = E;
}

// fill CSR buckets: col = src, wsrc = dinv[src]
__global__ void fill_kernel(int E) {
    int e = blockIdx.x * blockDim.x + threadIdx.x;
    if (e >= E) return;
    int s = g_eidx[e];
    int d = g_eidx[E + e];
    int pos = g_rowptr[d] + atomicAdd(&g_cnt[d], 1);
    g_col[pos] = s;
    g_wsrc[pos] = g_dinv[s];
}

// ---------------- TF32 tensor-core GEMM (fp16 output) ----------------
// C[M,N] = act(A[M,128]) @ W[128,N], C stored fp16
// LAYER2=false: A=Ain (x), C=g_h1h, no activation
// LAYER2=true : A=g_agg1 (fp32 symbol), C=g_h2h, A-load fused with +b1,relu
template <int N, bool LAYER2>
__global__ __launch_bounds__(256)
void mma_gemm_kernel(const float* __restrict__ Ain, const float* __restrict__ W,
                     const float* __restrict__ bias, int M) {
    constexpr int K = 128, BM = 128, BK = 32;
    constexpr int ASTR = 36;
    constexpr int WSTR = N + 8;
    constexpr int NT = N / 8;

    __shared__ alignas(16) uint32_t As[BM][ASTR];
    __shared__ alignas(16) uint32_t Ws[BK][WSTR];
    __shared__ alignas(16) float bsh[K];

    const float* A = LAYER2 ? (const float*)g_agg1 : Ain;
    __half* C = LAYER2 ? g_h2h : g_h1h;

    const int tid = threadIdx.x;
    const int warp = tid >> 5;
    const int lane = tid & 31;
    const int gid = lane >> 2;
    const int tig = lane & 3;
    const int row0 = blockIdx.x * BM;

    if (LAYER2) {
        if (tid < K) bsh[tid] = bias[tid];
        __syncthreads();
    }

    float acc[NT][4];
#pragma unroll
    for (int nt = 0; nt < NT; nt++)
#pragma unroll
        for (int j = 0; j < 4; j++) acc[nt][j] = 0.0f;

    for (int k0 = 0; k0 < K; k0 += BK) {
#pragma unroll
        for (int i = 0; i < 4; i++) {
            int t = tid + i * 256;
            int r = t >> 3;
            int c4 = t & 7;
            int grow = row0 + r;
            float4 v = make_float4(0.f, 0.f, 0.f, 0.f);
            if (grow < M)
                v = *reinterpret_cast<const float4*>(&A[(size_t)grow * K + k0 + c4 * 4]);
            if constexpr (LAYER2) {
                int kk = k0 + c4 * 4;
                v.x = fmaxf(v.x + bsh[kk + 0], 0.f);
                v.y = fmaxf(v.y + bsh[kk + 1], 0.f);
                v.z = fmaxf(v.z + bsh[kk + 2], 0.f);
                v.w = fmaxf(v.w + bsh[kk + 3], 0.f);
            }
            uint4 u = make_uint4(f2tf(v.x), f2tf(v.y), f2tf(v.z), f2tf(v.w));
            *reinterpret_cast<uint4*>(&As[r][c4 * 4]) = u;
        }
#pragma unroll
        for (int i = 0; i < (BK * N) / (256 * 4); i++) {
            int t = tid + i * 256;
            int r = t / (N / 4);
            int c4 = t % (N / 4);
            float4 v = *reinterpret_cast<const float4*>(&W[(size_t)(k0 + r) * N + c4 * 4]);
            uint4 u = make_uint4(f2tf(v.x), f2tf(v.y), f2tf(v.z), f2tf(v.w));
            *reinterpret_cast<uint4*>(&Ws[r][c4 * 4]) = u;
        }
        __syncthreads();

#pragma unroll
        for (int ks = 0; ks < BK / 8; ks++) {
            int kk = ks * 8;
            uint32_t a0 = As[warp * 16 + gid][kk + tig];
            uint32_t a1 = As[warp * 16 + gid + 8][kk + tig];
            uint32_t a2 = As[warp * 16 + gid][kk + tig + 4];
            uint32_t a3 = As[warp * 16 + gid + 8][kk + tig + 4];
#pragma unroll
            for (int nt = 0; nt < NT; nt++) {
                uint32_t b0 = Ws[kk + tig][nt * 8 + gid];
                uint32_t b1 = Ws[kk + tig + 4][nt * 8 + gid];
                mma_tf32(acc[nt], a0, a1, a2, a3, b0, b1);
            }
        }
        __syncthreads();
    }

    int r0 = row0 + warp * 16 + gid;
    int r1 = r0 + 8;
#pragma unroll
    for (int nt = 0; nt < NT; nt++) {
        int col = nt * 8 + tig * 2;
        if (r0 < M)
            *reinterpret_cast<__half2*>(&C[(size_t)r0 * N + col]) =
                __floats2half2_rn(acc[nt][0], acc[nt][1]);
        if (r1 < M)
            *reinterpret_cast<__half2*>(&C[(size_t)r1 * N + col]) =
                __floats2half2_rn(acc[nt][2], acc[nt][3]);
    }
}

// ---------------- CSR gather aggregation (fp16 inputs, fp32 accum/output) ----------------
// One warp per dst node d:
//   acc = sum_e wsrc[e] * h[col[e]];  out[d] = dinv[d]*acc + dinv[d]^2*h[d] (+ b2 layer 2)
// F==F1: h=g_h1h, out=g_agg1 (fp32, pre-bias/relu: GEMM2 fuses those).
// F==F2: h=g_h2h, out=outp (d_out), + b2.
template <int F>
__global__ void gather_kernel(const float* __restrict__ b2, float* __restrict__ outp, int n) {
    int d = (blockIdx.x * blockDim.x + threadIdx.x) >> 5;
    if (d >= n) return;
    int lane = threadIdx.x & 31;
    const __half* h = (F == F1) ? (const __half*)g_h1h : (const __half*)g_h2h;
    float* outb = (F == F1) ? (float*)g_agg1 : outp;
    constexpr int PER = F / 32;  // 4 or 2 halves per lane

    int beg = g_rowptr[d];
    int end = g_rowptr[d + 1];
    float di = g_dinv[d];

    float a0 = 0.f, a1 = 0.f, a2 = 0.f, a3 = 0.f;
    for (int base = beg; base < end; base += 32) {
        int idx = 0; float w = 0.f;
        int m = end - base;
        if (lane < m) { idx = g_col[base + lane]; w = g_wsrc[base + lane]; }
        int cnt = m < 32 ? m : 32;
        for (int j = 0; j < cnt; j++) {
            int s = __shfl_sync(0xffffffffu, idx, j);
            float ww = __shfl_sync(0xffffffffu, w, j);
            const __half* hs = h + (size_t)s * F + lane * PER;
            if (PER == 4) {
                uint2 u = *reinterpret_cast<const uint2*>(hs);
                float2 f0 = __half22float2(*reinterpret_cast<const __half2*>(&u.x));
                float2 f1 = __half22float2(*reinterpret_cast<const __half2*>(&u.y));
                a0 = fmaf(ww, f0.x, a0); a1 = fmaf(ww, f0.y, a1);
                a2 = fmaf(ww, f1.x, a2); a3 = fmaf(ww, f1.y, a3);
            } else {
                uint32_t u = *reinterpret_cast<const uint32_t*>(hs);
                float2 f0 = __half22float2(*reinterpret_cast<const __half2*>(&u));
                a0 = fmaf(ww, f0.x, a0); a1 = fmaf(ww, f0.y, a1);
            }
        }
    }

    // self-loop + scale (+ bias for layer 2)
    const __half* hd = h + (size_t)d * F + lane * PER;
    float* od = outb + (size_t)d * F + lane * PER;
    if (PER == 4) {
        uint2 u = *reinterpret_cast<const uint2*>(hd);
        float2 f0 = __half22float2(*reinterpret_cast<const __half2*>(&u.x));
        float2 f1 = __half22float2(*reinterpret_cast<const __half2*>(&u.y));
        float4 r;
        r.x = di * fmaf(di, f0.x, a0);
        r.y = di * fmaf(di, f0.y, a1);
        r.z = di * fmaf(di, f1.x, a2);
        r.w = di * fmaf(di, f1.y, a3);
        *reinterpret_cast<float4*>(od) = r;
    } else {
        uint32_t u = *reinterpret_cast<const uint32_t*>(hd);
        float2 f0 = __half22float2(*reinterpret_cast<const __half2*>(&u));
        float2 b = *reinterpret_cast<const float2*>(&b2[lane * PER]);
        float2 r;
        r.x = di * fmaf(di, f0.x, a0) + b.x;
        r.y = di * fmaf(di, f0.y, a1) + b.y;
        *reinterpret_cast<float2*>(od) = r;
    }
}

extern "C" void kernel_launch(void* const* d_in, const int* in_sizes, int n_in,
                              void* d_out, int out_size) {
    const float* x = (const float*)d_in[0];
    const void* ei = d_in[1];
    const float* W1 = (const float*)d_in[2];
    const float* b1 = (const float*)d_in[3];
    const float* W2 = (const float*)d_in[4];
    const float* b2 = (const float*)d_in[5];
    float* out = (float*)d_out;

    const int n = in_sizes[0] / F1;
    const int E = in_sizes[1] / 2;

    const int T = 256;
    // edge index: detect dtype (+ zero degrees), normalize to int32 (+ degree count fused)
    detect_zero_kernel<<<1, 1>>>();
    detect_kernel<<<256, T>>>(ei, E, n);
    convert_kernel<<<(2 * E + T - 1) / T, T>>>(ei, E, n);

    // CSR build: exclusive scan -> dinv -> bucket fill
    int nb = (n + SCAN_T - 1) / SCAN_T;
    scan1_kernel<<<nb, SCAN_T>>>(n);
    scan2_kernel<<<1, 1024>>>(nb);
    scan3_kernel<<<(n + T - 1) / T, T>>>(n, E);
    fill_kernel<<<(E + T - 1) / T, T>>>(E);

    // layer 1: g_h1h = x @ W1  (tf32 tensor cores, fp16 output)
    mma_gemm_kernel<128, false><<<(n + 127) / 128, 256>>>(x, W1, nullptr, n);
    // g_agg1 = D^-1/2 (A+I) D^-1/2 h1   (CSR gather, fp16 reads, fp32 out)
    gather_kernel<F1><<<(n * 32 + T - 1) / T, T>>>(nullptr, nullptr, n);

    // layer 2: g_h2h = relu(g_agg1 + b1) @ W2  (bias+relu fused into A-load)
    mma_gemm_kernel<64, true><<<(n + 127) / 128, 256>>>(nullptr, W2, b1, n);
    // out = D^-1/2 (A+I) D^-1/2 h2 + b2   (CSR gather, writes d_out fp32)
    gather_kernel<F2><<<(n * 32 + T - 1) / T, T>>>(b2, out, n);
}